// round 17
// baseline (speedup 1.0000x reference)
#include <cuda_runtime.h>
#include <cstdint>

#define B_ 128
#define T_ 1024
#define I_ 128
#define H_ 256
#define O_ 64

// Scratch (device globals — no allocations allowed)
__device__ float g_xw[(size_t)B_ * T_ * H_];  // 128 MB: x @ W_xh^T + b_h
__device__ float g_hs[(size_t)B_ * T_ * H_];  // 128 MB: hidden states

// ---------------------------------------------------------------------------
// Packed f32x2 + cluster helpers
// ---------------------------------------------------------------------------
__device__ __forceinline__ void ffma2(unsigned long long &acc,
                                      unsigned long long a,
                                      unsigned long long b) {
    asm("fma.rn.f32x2 %0, %1, %2, %0;" : "+l"(acc) : "l"(a), "l"(b));
}
__device__ __forceinline__ unsigned long long dup2(float a) {
    unsigned long long r;
    asm("mov.b64 %0, {%1, %1};" : "=l"(r) : "f"(a));
    return r;
}
__device__ __forceinline__ float2 unpack2(unsigned long long v) {
    float2 r;
    asm("mov.b64 {%0, %1}, %2;" : "=f"(r.x), "=f"(r.y) : "l"(v));
    return r;
}
__device__ __forceinline__ uint32_t smem_u32(const void* p) {
    uint32_t a;
    asm("{ .reg .u64 t; cvta.to.shared.u64 t, %1; cvt.u32.u64 %0, t; }"
        : "=r"(a) : "l"(p));
    return a;
}
__device__ __forceinline__ uint32_t ctarank() {
    uint32_t r;
    asm("mov.u32 %0, %%cluster_ctarank;" : "=r"(r));
    return r;
}
__device__ __forceinline__ uint32_t mapa_u32(uint32_t local, uint32_t rank) {
    uint32_t r;
    asm("mapa.shared::cluster.u32 %0, %1, %2;" : "=r"(r) : "r"(local), "r"(rank));
    return r;
}
__device__ __forceinline__ void st_remote_f32(uint32_t addr, float v) {
    asm volatile("st.shared::cluster.f32 [%0], %1;" :: "r"(addr), "f"(v) : "memory");
}
__device__ __forceinline__ void arrive_remote(uint32_t rbar) {
    asm volatile("mbarrier.arrive.release.cluster.shared::cluster.b64 _, [%0];"
                 :: "r"(rbar) : "memory");
}
__device__ __forceinline__ void mbar_init(uint32_t bar, uint32_t cnt) {
    asm volatile("mbarrier.init.shared.b64 [%0], %1;" :: "r"(bar), "r"(cnt) : "memory");
}
__device__ __forceinline__ void mbar_wait_acq_cluster(uint32_t bar, uint32_t parity) {
    asm volatile(
        "{\n\t.reg .pred P;\n\t"
        "WL_%=:\n\t"
        "mbarrier.try_wait.parity.acquire.cluster.shared::cta.b64 P, [%0], %1, 0x989680;\n\t"
        "@P bra.uni WD_%=;\n\t"
        "bra.uni WL_%=;\n\t"
        "WD_%=:\n\t}"
        :: "r"(bar), "r"(parity) : "memory");
}
#define CLUSTER_SYNC() do { \
    asm volatile("barrier.cluster.arrive.aligned;" ::: "memory"); \
    asm volatile("barrier.cluster.wait.aligned;" ::: "memory"); \
} while (0)

// ---------------------------------------------------------------------------
// Phase 1 (R4 version, measured 213us): g_xw = x @ W_xh^T + b_h
// ---------------------------------------------------------------------------
#define P1_PAD 132
#define P1_SMEM ((128 * P1_PAD + 128 * P1_PAD) * 4)

__global__ __launch_bounds__(256, 1) void p1_kernel(
    const float* __restrict__ x, const float* __restrict__ Wxh,
    const float* __restrict__ bh) {
    extern __shared__ float sm[];
    float* As  = sm;
    float* BsT = sm + 128 * P1_PAD;
    const int tid = threadIdx.x;
    const int mt = blockIdx.x >> 1;
    const int nt = blockIdx.x & 1;

    const float* Ag = x + (size_t)mt * 128 * I_;
#pragma unroll
    for (int i = 0; i < 16; i++) {
        int lin = tid + 256 * i;
        int r = lin >> 5, c4 = lin & 31;
        float4 v = ((const float4*)Ag)[r * 32 + c4];
        *(float4*)(As + r * P1_PAD + c4 * 4) = v;
    }
    {
        int n = tid & 127, kg = tid >> 7;
        const float4* Bg = (const float4*)(Wxh + (size_t)(nt * 128 + n) * I_ + kg * 64);
#pragma unroll
        for (int q = 0; q < 16; q++) {
            float4 v = Bg[q];
            int kb = kg * 64 + q * 4;
            BsT[(kb + 0) * P1_PAD + n] = v.x;
            BsT[(kb + 1) * P1_PAD + n] = v.y;
            BsT[(kb + 2) * P1_PAD + n] = v.z;
            BsT[(kb + 3) * P1_PAD + n] = v.w;
        }
    }
    __syncthreads();

    const int tx = tid & 15, ty = tid >> 4;
    unsigned long long acc[8][4];
#pragma unroll
    for (int u = 0; u < 8; u++)
#pragma unroll
        for (int v = 0; v < 4; v++) acc[u][v] = 0ull;

#pragma unroll 4
    for (int k = 0; k < 128; k++) {
        unsigned long long a2[8], b2[4];
#pragma unroll
        for (int u = 0; u < 8; u++)
            a2[u] = dup2(As[(ty + 16 * u) * P1_PAD + k]);
#pragma unroll
        for (int v = 0; v < 4; v++)
            b2[v] = *(const unsigned long long*)(BsT + k * P1_PAD + 2 * tx + 32 * v);
#pragma unroll
        for (int u = 0; u < 8; u++)
#pragma unroll
            for (int v = 0; v < 4; v++) ffma2(acc[u][v], a2[u], b2[v]);
    }

    float2 bias[4];
#pragma unroll
    for (int v = 0; v < 4; v++)
        bias[v] = *(const float2*)(bh + nt * 128 + 2 * tx + 32 * v);
#pragma unroll
    for (int u = 0; u < 8; u++) {
        size_t row = (size_t)mt * 128 + ty + 16 * u;
        float* op = g_xw + row * H_ + nt * 128;
#pragma unroll
        for (int v = 0; v < 4; v++) {
            float2 r = unpack2(acc[u][v]);
            r.x += bias[v].x;
            r.y += bias[v].y;
            *(float2*)(op + 2 * tx + 32 * v) = r;
        }
    }
}

// ---------------------------------------------------------------------------
// Phase 2: cluster-split scan. 64 clusters x 2 CTAs x 256 threads.
// Cluster c handles batches 2c, 2c+1. CTA rank r owns k in [128r, 128r+128):
// thread h holds W_hh[h][k-half] entirely in 64 u64 registers (no W smem).
// Per step: compute half-k partials for both batches, exchange with peer via
// st.shared::cluster + mbarrier (double-buffered slots), combine + relu.
// smem: mbar[2] @0, pbuf[2][2][256] @128, hbuf[2][2][128] @4224.
// ---------------------------------------------------------------------------
#define RNN_SMEM (128 + 2 * 2 * H_ * 4 + 2 * 2 * 128 * 4)

__global__ __launch_bounds__(256, 1) __cluster_dims__(2, 1, 1)
void rnn_kernel(const float* __restrict__ Whh) {
    extern __shared__ char smraw[];
    float* pbuf = (float*)(smraw + 128);                     // [2][2][H_]
    float* hbuf = (float*)(smraw + 128 + 2 * 2 * H_ * 4);    // [2][2][128]
    const int h = threadIdx.x;
    const uint32_t rank = ctarank();
    const int cid = blockIdx.x >> 1;
    const int b0 = 2 * cid, b1 = b0 + 1;

    const uint32_t sbase = smem_u32(smraw);
    const uint32_t bar0 = sbase, bar1 = sbase + 8;

    // W half-row into registers: k in [rank*128, rank*128+128)
    const unsigned long long* wrow =
        (const unsigned long long*)(Whh + (size_t)h * H_ + rank * 128);
    unsigned long long wreg[64];
#pragma unroll
    for (int j = 0; j < 64; j++) wreg[j] = wrow[j];

    if (h == 0) { mbar_init(bar0, 256); mbar_init(bar1, 256); }
    hbuf[h] = 0.0f;        // zero both buffers (512 floats total)
    hbuf[256 + h] = 0.0f;
    __syncthreads();
    CLUSTER_SYNC();  // peer mbarriers initialized before any remote arrive

    // remote addresses in peer CTA
    const uint32_t peer = rank ^ 1;
    const uint32_t r_pbuf = mapa_u32(sbase + 128, peer);
    const uint32_t r_bar[2] = {mapa_u32(bar0, peer), mapa_u32(bar1, peer)};

    const float* xwp0 = g_xw + (size_t)b0 * T_ * H_ + h;
    const float* xwp1 = g_xw + (size_t)b1 * T_ * H_ + h;
    float* hsp0 = g_hs + (size_t)b0 * T_ * H_ + h;
    float* hsp1 = g_hs + (size_t)b1 * T_ * H_ + h;

    float xwf0[2], xwf1[2];
#pragma unroll
    for (int i = 0; i < 2; i++) {
        xwf0[i] = __ldg(xwp0 + (size_t)i * H_);
        xwf1[i] = __ldg(xwp1 + (size_t)i * H_);
    }

    const int own = ((h >> 7) == (int)rank);
    const int hl = h & 127;
    int cur = 0;

#pragma unroll 1
    for (int t = 0; t < T_; t++) {
        const int s = t & 1;
        const uint32_t par = (t >> 1) & 1;
        const ulonglong2* hc = (const ulonglong2*)(hbuf + cur * 256);

        unsigned long long a00 = 0ull, a01 = 0ull, a10 = 0ull, a11 = 0ull;
#pragma unroll
        for (int j = 0; j < 32; j++) {
            ulonglong2 v0 = hc[j];        // batch 0 half-h, broadcast
            ulonglong2 v1 = hc[32 + j];   // batch 1 half-h, broadcast
            ffma2(a00, v0.x, wreg[2 * j]);
            ffma2(a01, v0.y, wreg[2 * j + 1]);
            ffma2(a10, v1.x, wreg[2 * j]);
            ffma2(a11, v1.y, wreg[2 * j + 1]);
        }
        float2 c00 = unpack2(a00), c01 = unpack2(a01);
        float2 c10 = unpack2(a10), c11 = unpack2(a11);
        float p0 = (c00.x + c00.y) + (c01.x + c01.y);
        float p1 = (c10.x + c10.y) + (c11.x + c11.y);

        // send partials to peer slot s, then release-arrive on peer's bar[s]
        st_remote_f32(r_pbuf + (uint32_t)(s * 2 * H_ + h) * 4, p0);
        st_remote_f32(r_pbuf + (uint32_t)(s * 2 * H_ + H_ + h) * 4, p1);
        arrive_remote(r_bar[s]);

        // wait for peer's 256 partials (acquire at cluster scope)
        mbar_wait_acq_cluster(sbase + 8 * s, par);

        float q0 = pbuf[s * 2 * H_ + h];
        float q1 = pbuf[s * 2 * H_ + H_ + h];
        float hn0 = fmaxf(xwf0[t & 1] + p0 + q0, 0.0f);
        float hn1 = fmaxf(xwf1[t & 1] + p1 + q1, 0.0f);

        if (own) {
            hbuf[(cur ^ 1) * 256 + hl] = hn0;
            hbuf[(cur ^ 1) * 256 + 128 + hl] = hn1;
        }
        if (rank == 0) {
            hsp0[(size_t)t * H_] = hn0;
            hsp1[(size_t)t * H_] = hn1;
        }
        xwf0[t & 1] = __ldg(xwp0 + (size_t)((t + 2) & (T_ - 1)) * H_);
        xwf1[t & 1] = __ldg(xwp1 + (size_t)((t + 2) & (T_ - 1)) * H_);
        cur ^= 1;
        __syncthreads();
    }
    CLUSTER_SYNC();  // keep peer smem alive until all remote ops consumed
}

// ---------------------------------------------------------------------------
// Phase 3 (R4 version, measured ~90us): out = g_hs @ W_out^T + b_out
// ---------------------------------------------------------------------------
#define P3_WPAD 66
#define P3_APAD 68
#define P3_SMEM ((256 * P3_WPAD + 128 * P3_APAD) * 4)

__global__ __launch_bounds__(256, 1) void p3_kernel(
    const float* __restrict__ Wout, const float* __restrict__ bout,
    float* __restrict__ out) {
    extern __shared__ float sm[];
    float* WsT = sm;
    float* As  = sm + 256 * P3_WPAD;
    const int tid = threadIdx.x;
    const int mt = blockIdx.x;

    {
        int o = tid >> 2, kq = tid & 3;
        const float4* Wg = (const float4*)(Wout + (size_t)o * H_ + kq * 64);
#pragma unroll
        for (int q = 0; q < 16; q++) {
            float4 v = Wg[q];
            int kb = kq * 64 + q * 4;
            WsT[(kb + 0) * P3_WPAD + o] = v.x;
            WsT[(kb + 1) * P3_WPAD + o] = v.y;
            WsT[(kb + 2) * P3_WPAD + o] = v.z;
            WsT[(kb + 3) * P3_WPAD + o] = v.w;
        }
    }

    const int tx = tid & 15, ty = tid >> 4;
    unsigned long long acc[8][2];
#pragma unroll
    for (int u = 0; u < 8; u++) { acc[u][0] = 0ull; acc[u][1] = 0ull; }

    for (int kc = 0; kc < 4; kc++) {
        __syncthreads();
#pragma unroll
        for (int i = 0; i < 8; i++) {
            int lin = tid + 256 * i;
            int r = lin >> 4, c4 = lin & 15;
            float4 v = *(const float4*)(g_hs + ((size_t)mt * 128 + r) * H_ +
                                        kc * 64 + c4 * 4);
            *(float4*)(As + r * P3_APAD + c4 * 4) = v;
        }
        __syncthreads();
#pragma unroll 4
        for (int k = 0; k < 64; k++) {
            unsigned long long b0 = *(const unsigned long long*)(
                WsT + (kc * 64 + k) * P3_WPAD + 2 * tx);
            unsigned long long b1 = *(const unsigned long long*)(
                WsT + (kc * 64 + k) * P3_WPAD + 2 * tx + 32);
#pragma unroll
            for (int u = 0; u < 8; u++) {
                unsigned long long a2 = dup2(As[(ty + 16 * u) * P3_APAD + k]);
                ffma2(acc[u][0], a2, b0);
                ffma2(acc[u][1], a2, b1);
            }
        }
    }

    float2 bias0 = *(const float2*)(bout + 2 * tx);
    float2 bias1 = *(const float2*)(bout + 2 * tx + 32);
#pragma unroll
    for (int u = 0; u < 8; u++) {
        size_t row = (size_t)mt * 128 + ty + 16 * u;
        float2 r0 = unpack2(acc[u][0]);
        float2 r1 = unpack2(acc[u][1]);
        r0.x += bias0.x; r0.y += bias0.y;
        r1.x += bias1.x; r1.y += bias1.y;
        *(float2*)(out + row * O_ + 2 * tx) = r0;
        *(float2*)(out + row * O_ + 2 * tx + 32) = r1;
    }
}

// ---------------------------------------------------------------------------
extern "C" void kernel_launch(void* const* d_in, const int* in_sizes, int n_in,
                              void* d_out, int out_size) {
    const float* x    = (const float*)d_in[0];
    const float* Wxh  = (const float*)d_in[1];
    const float* Whh  = (const float*)d_in[2];
    const float* bh   = (const float*)d_in[3];
    const float* Wout = (const float*)d_in[4];
    const float* bout = (const float*)d_in[5];
    float* out = (float*)d_out;

    cudaFuncSetAttribute(p1_kernel, cudaFuncAttributeMaxDynamicSharedMemorySize, P1_SMEM);
    cudaFuncSetAttribute(rnn_kernel, cudaFuncAttributeMaxDynamicSharedMemorySize, RNN_SMEM);
    cudaFuncSetAttribute(p3_kernel, cudaFuncAttributeMaxDynamicSharedMemorySize, P3_SMEM);

    p1_kernel<<<(B_ * T_ / 128) * 2, 256, P1_SMEM>>>(x, Wxh, bh);
    rnn_kernel<<<B_, 256, RNN_SMEM>>>(Whh);   // 128 CTAs = 64 clusters of 2
    p3_kernel<<<B_ * T_ / 128, 256, P3_SMEM>>>(Wout, bout, out);
}